// round 10
// baseline (speedup 1.0000x reference)
#include <cuda_runtime.h>
#include <math.h>

#define H_   2048
#define HQ_  16
#define HKV_ 8
#define DH_  128
#define CHUNK_ 128
#define MAXCH_ 128
#define GRID_ 592                       // 148 SMs x 4 resident blocks
#define SCALE_ 0.08838834764831845f    // 1/sqrt(128)
#define EPS_ 1e-6f

// ------------------------- scratch (device globals, no allocs) --------------
__device__ float g_proj[4096];                 // raw q(2048) | k(1024) | v(1024)
__device__ float g_q[HQ_*DH_];                 // normed+roped q
__device__ float g_k[HKV_*DH_];                // normed+roped k_new
__device__ float g_v[HKV_*DH_];                // v_new
__device__ float g_m[HQ_*MAXCH_];
__device__ float g_l[HQ_*MAXCH_];
__device__ float g_acc[HQ_*MAXCH_*DH_];
__device__ float g_attn[HQ_*DH_];              // attention out, head-major

// barrier + work-queue state (epoch-based; survives graph replays)
__device__ unsigned g_bar_count = 0;
__device__ volatile unsigned g_bar_epoch = 0;
__device__ unsigned g_task = 0;                // reset in P0 each launch

__device__ __forceinline__ void gridBarrier() {
    __syncthreads();
    if (threadIdx.x == 0) {
        unsigned e = g_bar_epoch;
        __threadfence();
        unsigned r = atomicAdd(&g_bar_count, 1u);
        if (r == gridDim.x - 1) {
            g_bar_count = 0;
            __threadfence();
            g_bar_epoch = e + 1;
        } else {
            while (g_bar_epoch == e) __nanosleep(64);
        }
        __threadfence();
    }
    __syncthreads();
}

__device__ __forceinline__ float warpSum(float v) {
    #pragma unroll
    for (int o = 16; o; o >>= 1) v += __shfl_xor_sync(0xffffffffu, v, o);
    return v;
}
__device__ __forceinline__ float warpMax(float v) {
    #pragma unroll
    for (int o = 16; o; o >>= 1) v = fmaxf(v, __shfl_xor_sync(0xffffffffu, v, o));
    return v;
}

__device__ __forceinline__ float blockSum256(float v, float* red, int t) {
    float ws = warpSum(v);
    if ((t & 31) == 0) red[t >> 5] = ws;
    __syncthreads();
    float r = (t < 8) ? red[t] : 0.f;
    r = warpSum(r);
    if (t == 0) red[8] = r;
    __syncthreads();
    float out = red[8];
    __syncthreads();
    return out;
}
__device__ __forceinline__ float blockMax256(float v, float* red, int t) {
    float ws = warpMax(v);
    if ((t & 31) == 0) red[t >> 5] = ws;
    __syncthreads();
    float r = (t < 8) ? red[t] : -INFINITY;
    r = warpMax(r);
    if (t == 0) red[8] = r;
    __syncthreads();
    float out = red[8];
    __syncthreads();
    return out;
}

// ------------------------- the persistent kernel ----------------------------
__global__ void __launch_bounds__(256, 4) k_fused(
        const float* __restrict__ x,
        const float* __restrict__ cosv,
        const float* __restrict__ sinv,
        const float* __restrict__ mask,
        const float* __restrict__ kc,
        const float* __restrict__ vc,
        const float* __restrict__ Wq,
        const float* __restrict__ Wk,
        const float* __restrict__ Wv,
        const float* __restrict__ Wo,
        const float* __restrict__ qw,
        const float* __restrict__ kw,
        float* __restrict__ out,
        int C, int nchunks) {
    int bx = blockIdx.x;
    int t = threadIdx.x;
    int warp = t >> 5, lane = t & 31;
    int ntasks = nchunks * HKV_;

    // ============ P0: QKV projection (warp-per-row) + queue reset ===========
    if (bx == 0 && t == 0) g_task = 0;
    {
        int e = bx * 8 + warp;                 // 0..4735 (4096 real)
        if (e < 4096) {
            const float* W = (e < 2048) ? (Wq + (size_t)e * H_)
                           : (e < 3072) ? (Wk + (size_t)(e - 2048) * H_)
                                        : (Wv + (size_t)(e - 3072) * H_);
            const float4* W4 = (const float4*)W;
            const float4* x4 = (const float4*)x;
            float acc = 0.f;
            #pragma unroll
            for (int i = 0; i < 16; i++) {
                float4 w  = W4[lane + i * 32];
                float4 xv = x4[lane + i * 32];
                acc += w.x * xv.x + w.y * xv.y + w.z * xv.z + w.w * xv.w;
            }
            acc = warpSum(acc);
            if (lane == 0) g_proj[e] = acc;
        }
    }
    gridBarrier();

    // ============ P1: RMSNorm + RoPE + output copies ========================
    if (bx < 24) {                             // q heads (0..15), k heads (16..23)
        __shared__ float sx2[DH_];
        __shared__ float red2[8];
        int b = bx;
        bool isq = (b < 16);
        float xv = (t < 128) ? g_proj[b * DH_ + t] : 0.f;
        float ws = warpSum(xv * xv);
        if ((t & 31) == 0) red2[t >> 5] = ws;
        __syncthreads();
        float ssum = red2[0] + red2[1] + red2[2] + red2[3];
        float rms = sqrtf(ssum * (1.0f / DH_) + EPS_);
        float xn = (t < 128) ? xv / rms * (isq ? qw[t] : kw[t]) : 0.f;
        if (t < 128) sx2[t] = xn;
        __syncthreads();
        if (t < 128) {
            float rot = (t < 64) ? -sx2[t + 64] : sx2[t - 64];
            float o = xn * cosv[t] + rot * sinv[t];
            if (isq) {
                g_q[b * DH_ + t] = o;
            } else {
                int kv = b - 16;
                g_k[kv * DH_ + t] = o;
                out[2048 + kv * DH_ + t] = o;
            }
        }
    } else if (bx < 32 && t < 128) {           // v copies
        int kv = bx - 24;
        float v = g_proj[3072 + kv * DH_ + t];
        g_v[kv * DH_ + t] = v;
        out[3072 + kv * DH_ + t] = v;
    }
    gridBarrier();

    // ============ P2: attention partial — work-stealing queue ===============
    {
        __shared__ int sTask;
        __shared__ float q0s[DH_], q1s[DH_];
        __shared__ float sA0[256], sA1[256];
        __shared__ float p0s[CHUNK_], p1s[CHUNK_];
        __shared__ float red[16];
        __shared__ float vred[256];

        for (;;) {
            __syncthreads();
            if (t == 0) sTask = (int)atomicAdd(&g_task, 1u);
            __syncthreads();
            int j = sTask;
            if (j >= ntasks) break;
            int chunk = j % nchunks;
            int kv = j / nchunks;

            if (t < DH_) {
                q0s[t] = g_q[(kv * 2) * DH_ + t];
                q1s[t] = g_q[(kv * 2 + 1) * DH_ + t];
            }
            __syncthreads();

            // --- score: split-dot, 2 thread-groups x 64 dims each -----------
            int cc = t & 127;
            int dh = t >> 7;                    // 0/1
            int c = chunk * CHUNK_ + cc;
            float a0 = 0.f, a1 = 0.f;
            if (c < C) {
                const float* kbase = kc + ((size_t)kv * DH_ + dh * 64) * C + c;
                #pragma unroll 16
                for (int d = 0; d < 64; d++) {
                    float kval = kbase[(size_t)d * C];
                    a0 += q0s[dh * 64 + d] * kval;
                    a1 += q1s[dh * 64 + d] * kval;
                }
            }
            sA0[t] = a0; sA1[t] = a1;
            __syncthreads();
            float s0 = -INFINITY, s1 = -INFINITY;
            if (t < 128 && c < C) {
                float mval = mask[c];
                s0 = (sA0[t] + sA0[t + 128]) * SCALE_ + mval;
                s1 = (sA1[t] + sA1[t + 128]) * SCALE_ + mval;
            }
            float m0 = blockMax256(s0, red, t);
            float m1 = blockMax256(s1, red, t);
            float p0 = (s0 == -INFINITY) ? 0.f : expf(s0 - m0);
            float p1 = (s1 == -INFINITY) ? 0.f : expf(s1 - m1);
            float l0 = blockSum256(p0, red, t);
            float l1 = blockSum256(p1, red, t);
            if (t < 128) { p0s[t] = p0; p1s[t] = p1; }
            __syncthreads();

            // --- V accumulation: d = t&127, 2 row-stripes -------------------
            int d = t & 127;
            int rg = t >> 7;
            int rows = C - chunk * CHUNK_;
            if (rows > CHUNK_) rows = CHUNK_;
            const float* vbase = vc + (size_t)kv * C * DH_
                               + (size_t)chunk * CHUNK_ * DH_ + d;
            float va0 = 0.f, va1 = 0.f;
            #pragma unroll 8
            for (int r = rg; r < rows; r += 2) {
                float vv = vbase[(size_t)r * DH_];
                va0 += p0s[r] * vv;
                va1 += p1s[r] * vv;
            }
            vred[t] = va0; __syncthreads();
            float tot0 = (t < 128) ? (vred[t] + vred[t + 128]) : 0.f;
            __syncthreads();
            vred[t] = va1; __syncthreads();
            float tot1 = (t < 128) ? (vred[t] + vred[t + 128]) : 0.f;

            int idx0 = (kv * 2) * MAXCH_ + chunk;
            int idx1 = idx0 + MAXCH_;
            if (t == 0) { g_m[idx0] = m0; g_l[idx0] = l0; g_m[idx1] = m1; g_l[idx1] = l1; }
            if (t < 128) {
                g_acc[(size_t)idx0 * DH_ + t] = tot0;
                g_acc[(size_t)idx1 * DH_ + t] = tot1;
            }
        }
    }
    gridBarrier();

    // ============ P3: combine partials (blocks 0..15) =======================
    if (bx < HQ_) {
        int qh = bx;
        int kv = qh >> 1;
        __shared__ float sm[MAXCH_], sl[MAXCH_], sw[MAXCH_];
        __shared__ float red3[8];
        __shared__ float sMax, sSnew, sL;
        __shared__ float vacc[256];

        if (t < nchunks) { sm[t] = g_m[qh * MAXCH_ + t]; sl[t] = g_l[qh * MAXCH_ + t]; }
        if (t < 128) {
            float prod = g_q[qh * DH_ + t] * g_k[kv * DH_ + t];
            float ws = warpSum(prod);
            if ((t & 31) == 0) red3[t >> 5] = ws;
        }
        __syncthreads();
        // parallel max over chunks
        if (t < 64) {
            float mv = -INFINITY;
            for (int j = t; j < nchunks; j += 64) mv = fmaxf(mv, sm[j]);
            mv = warpMax(mv);
            if (t == 0)  red3[4] = mv;
            if (t == 32) red3[5] = mv;
        }
        __syncthreads();
        if (t == 0) {
            float dot = red3[0] + red3[1] + red3[2] + red3[3];
            float s_new = dot * SCALE_ + mask[C];
            sSnew = s_new;
            sMax = fmaxf(fmaxf(red3[4], red3[5]), s_new);
        }
        __syncthreads();
        float M = sMax;
        if (t < nchunks) sw[t] = expf(sm[t] - M);
        __syncthreads();
        if (t < 64) {
            float lv = 0.f;
            for (int j = t; j < nchunks; j += 64) lv += sw[j] * sl[j];
            float ws = warpSum(lv);
            if (t == 0)  red3[4] = ws;
            if (t == 32) red3[5] = ws;
        }
        __syncthreads();
        if (t == 0) sL = expf(sSnew - M) + red3[4] + red3[5];
        __syncthreads();

        int d = t & 127;
        int cg = t >> 7;                       // 0..1
        const float* accb = g_acc + (size_t)qh * MAXCH_ * DH_ + d;
        float a = 0.f;
        #pragma unroll 8
        for (int j = cg; j < nchunks; j += 2)
            a += sw[j] * accb[(size_t)j * DH_];
        vacc[t] = a;
        __syncthreads();
        if (t < 128) {
            float wnew = expf(sSnew - M);
            float tot = vacc[t] + vacc[t + 128] + wnew * g_v[kv * DH_ + t];
            g_attn[qh * DH_ + t] = tot / sL;
        }
    }
    gridBarrier();

    // ============ P4: o_proj — 4 rows/block, 2 warps per row ================
    if (bx < 512) {
        __shared__ float s4[8];
        int r = bx * 4 + (warp >> 1);          // output row
        int h = warp & 1;                      // half of the dot
        const float4* W4 = (const float4*)(Wo + (size_t)r * (HQ_ * DH_) + h * 1024);
        const float4* a4 = (const float4*)(g_attn) + h * 256;
        float acc = 0.f;
        #pragma unroll
        for (int k = 0; k < 8; k++) {
            float4 w = W4[lane + k * 32];
            float4 a = a4[lane + k * 32];
            acc += w.x * a.x + w.y * a.y + w.z * a.z + w.w * a.w;
        }
        acc = warpSum(acc);
        if (lane == 0) s4[warp] = acc;
        __syncthreads();
        if (t < 4) out[bx * 4 + t] = s4[2 * t] + s4[2 * t + 1];
    }
}

// ------------------------- launch --------------------------------------------
extern "C" void kernel_launch(void* const* d_in, const int* in_sizes, int n_in,
                              void* d_out, int out_size) {
    const float* x     = (const float*)d_in[0];
    const float* cosv  = (const float*)d_in[1];
    const float* sinv  = (const float*)d_in[2];
    const float* mask  = (const float*)d_in[3];
    const float* kc    = (const float*)d_in[4];
    const float* vc    = (const float*)d_in[5];
    const float* Wq    = (const float*)d_in[6];
    const float* Wk    = (const float*)d_in[7];
    const float* Wv    = (const float*)d_in[8];
    const float* Wo    = (const float*)d_in[9];
    const float* qw    = (const float*)d_in[10];
    const float* kw    = (const float*)d_in[11];
    float* out = (float*)d_out;

    int C = in_sizes[4] / (HKV_ * DH_);           // 16384
    int nchunks = (C + CHUNK_ - 1) / CHUNK_;      // 128
    if (nchunks > MAXCH_) nchunks = MAXCH_;

    k_fused<<<GRID_, 256>>>(x, cosv, sinv, mask, kc, vc,
                            Wq, Wk, Wv, Wo, qw, kw, out, C, nchunks);
}

// round 11
// speedup vs baseline: 1.3304x; 1.3304x over previous
#include <cuda_runtime.h>
#include <math.h>

#define H_   2048
#define HQ_  16
#define HKV_ 8
#define DH_  128
#define CHUNK_ 256
#define MAXCH_ 128
#define SCALE_ 0.08838834764831845f   // 1/sqrt(128)
#define EPS_ 1e-6f

// ------------------------- scratch (device globals, no allocs) --------------
__device__ float g_proj[4096];                 // raw q(2048) | k(1024) | v(1024)
__device__ float g_q[HQ_*DH_];                 // normed+roped q
__device__ float g_k[HKV_*DH_];                // normed+roped k_new
__device__ float g_v[HKV_*DH_];                // v_new
__device__ float g_m[HQ_*MAXCH_];
__device__ float g_l[HQ_*MAXCH_];
__device__ float g_acc[HQ_*MAXCH_*DH_];
__device__ float g_attn[HQ_*DH_];              // attention out, head-major

__device__ __forceinline__ float warpSum(float v) {
    #pragma unroll
    for (int o = 16; o; o >>= 1) v += __shfl_xor_sync(0xffffffffu, v, o);
    return v;
}
__device__ __forceinline__ float warpMax(float v) {
    #pragma unroll
    for (int o = 16; o; o >>= 1) v = fmaxf(v, __shfl_xor_sync(0xffffffffu, v, o));
    return v;
}

__device__ __forceinline__ float blockSum256(float v, float* red, int t) {
    float ws = warpSum(v);
    if ((t & 31) == 0) red[t >> 5] = ws;
    __syncthreads();
    float r = (t < 8) ? red[t] : 0.f;
    r = warpSum(r);
    if (t == 0) red[8] = r;
    __syncthreads();
    float out = red[8];
    __syncthreads();
    return out;
}
__device__ __forceinline__ float blockMax256(float v, float* red, int t) {
    float ws = warpMax(v);
    if ((t & 31) == 0) red[t >> 5] = ws;
    __syncthreads();
    float r = (t < 8) ? red[t] : -INFINITY;
    r = warpMax(r);
    if (t == 0) red[8] = r;
    __syncthreads();
    float out = red[8];
    __syncthreads();
    return out;
}

// ------------------------- 1: QKV projection (R2 shape) ----------------------
__global__ void k_proj(const float* __restrict__ x,
                       const float* __restrict__ Wq,
                       const float* __restrict__ Wk,
                       const float* __restrict__ Wv) {
    int e = blockIdx.x;
    const float* W = (e < 2048) ? (Wq + (size_t)e * H_)
                   : (e < 3072) ? (Wk + (size_t)(e - 2048) * H_)
                                : (Wv + (size_t)(e - 3072) * H_);
    int t = threadIdx.x;
    const float4* W4 = (const float4*)W;
    const float4* x4 = (const float4*)x;
    float acc = 0.f;
    #pragma unroll
    for (int k = 0; k < 4; k++) {
        float4 w  = W4[t + k * 128];
        float4 xv = x4[t + k * 128];
        acc += w.x * xv.x + w.y * xv.y + w.z * xv.z + w.w * xv.w;
    }
    __shared__ float s[4];
    float ws = warpSum(acc);
    if ((t & 31) == 0) s[t >> 5] = ws;
    __syncthreads();
    if (t == 0) g_proj[e] = s[0] + s[1] + s[2] + s[3];
}

// ------------------------- 2: RMSNorm + RoPE + copies (R2) -------------------
__global__ void k_norm_rope(const float* __restrict__ cosv,
                            const float* __restrict__ sinv,
                            const float* __restrict__ qw,
                            const float* __restrict__ kw,
                            float* __restrict__ out) {
    int b = blockIdx.x, t = threadIdx.x;
    const float* row = g_proj + b * DH_;
    if (b < 24) {
        bool isq = (b < 16);
        __shared__ float sx[DH_];
        __shared__ float red[8];
        float x = row[t];
        float ws = warpSum(x * x);
        if ((t & 31) == 0) red[t >> 5] = ws;
        __syncthreads();
        float ssum = red[0] + red[1] + red[2] + red[3];
        float rms = sqrtf(ssum * (1.0f / DH_) + EPS_);
        float xn = x / rms * (isq ? qw[t] : kw[t]);
        sx[t] = xn;
        __syncthreads();
        float rot = (t < 64) ? -sx[t + 64] : sx[t - 64];
        float o = xn * cosv[t] + rot * sinv[t];
        if (isq) {
            g_q[b * DH_ + t] = o;
        } else {
            int kv = b - 16;
            g_k[kv * DH_ + t] = o;
            out[2048 + kv * DH_ + t] = o;   // k_new output
        }
    } else {
        int kv = b - 24;
        float v = row[t];
        g_v[kv * DH_ + t] = v;
        out[3072 + kv * DH_ + t] = v;       // v output
    }
}

// ------------------------- 3: attention partials (occupancy-boosted) ---------
// grid (nchunks, HKV) x 256 threads. launch_bounds(256,6) caps regs -> ~48
// warps/SM resident. Streaming loads (__ldcs) on the 134MB kc/vc stream.
__global__ void __launch_bounds__(256, 6) k_attn_partial(
                               const float* __restrict__ kc,
                               const float* __restrict__ vc,
                               const float* __restrict__ mask,
                               int C) {
    int chunk = blockIdx.x;
    int kv = blockIdx.y;
    int t = threadIdx.x;
    int c = chunk * CHUNK_ + t;
    bool valid = (c < C);

    __shared__ float q0s[DH_], q1s[DH_];
    __shared__ float p0s[CHUNK_], p1s[CHUNK_];
    __shared__ float red[16];
    __shared__ float vred[CHUNK_];

    if (t < DH_) {
        q0s[t] = g_q[(kv * 2) * DH_ + t];
        q1s[t] = g_q[(kv * 2 + 1) * DH_ + t];
    }
    __syncthreads();

    float a0 = 0.f, a1 = 0.f;
    if (valid) {
        const float* kbase = kc + (size_t)kv * DH_ * C + c;
        #pragma unroll 16
        for (int d = 0; d < DH_; d++) {
            float kval = __ldcs(kbase + (size_t)d * C);
            a0 += q0s[d] * kval;
            a1 += q1s[d] * kval;
        }
    }
    float mval = valid ? mask[c] : 0.f;
    float s0 = valid ? (a0 * SCALE_ + mval) : -INFINITY;
    float s1 = valid ? (a1 * SCALE_ + mval) : -INFINITY;

    float m0 = blockMax256(s0, red, t);
    float m1 = blockMax256(s1, red, t);
    float p0 = valid ? expf(s0 - m0) : 0.f;
    float p1 = valid ? expf(s1 - m1) : 0.f;
    float l0 = blockSum256(p0, red, t);
    float l1 = blockSum256(p1, red, t);
    p0s[t] = p0; p1s[t] = p1;
    __syncthreads();

    // V accumulation: thread t handles dim (t&127), positions (t>>7), step 2.
    int d = t & 127;
    int half = t >> 7;
    const float* vbase = vc + (size_t)kv * C * DH_ + (size_t)(chunk * CHUNK_) * DH_ + d;
    float va0 = 0.f, va1 = 0.f;
    int cmax = C - chunk * CHUNK_;
    if (cmax > CHUNK_) cmax = CHUNK_;
    #pragma unroll 8
    for (int cc = half; cc < cmax; cc += 2) {
        float vv = __ldcs(vbase + (size_t)cc * DH_);
        va0 += p0s[cc] * vv;
        va1 += p1s[cc] * vv;
    }
    vred[t] = va0; __syncthreads();
    float tot0 = (t < 128) ? (vred[t] + vred[t + 128]) : 0.f;
    __syncthreads();
    vred[t] = va1; __syncthreads();
    float tot1 = (t < 128) ? (vred[t] + vred[t + 128]) : 0.f;

    int idx0 = (kv * 2) * MAXCH_ + chunk;
    int idx1 = (kv * 2 + 1) * MAXCH_ + chunk;
    if (t == 0) { g_m[idx0] = m0; g_l[idx0] = l0; g_m[idx1] = m1; g_l[idx1] = l1; }
    if (t < 128) {
        g_acc[(size_t)idx0 * DH_ + t] = tot0;
        g_acc[(size_t)idx1 * DH_ + t] = tot1;
    }
}

// ------------------------- 4: combine partials + new token (R2) --------------
__global__ void __launch_bounds__(512) k_attn_reduce(
                              const float* __restrict__ mask,
                              int C, int nchunks) {
    int qh = blockIdx.x, t = threadIdx.x;
    int kv = qh >> 1;
    __shared__ float sm[MAXCH_], sl[MAXCH_], sw[MAXCH_];
    __shared__ float red[8];
    __shared__ float sMax, sSnew, sL;
    __shared__ float vacc[512];

    if (t < nchunks) { sm[t] = g_m[qh * MAXCH_ + t]; sl[t] = g_l[qh * MAXCH_ + t]; }

    if (t < 128) {
        float prod = g_q[qh * DH_ + t] * g_k[kv * DH_ + t];
        float ws = warpSum(prod);
        if ((t & 31) == 0) red[t >> 5] = ws;
    }
    __syncthreads();
    if (t == 0) {
        float dot = red[0] + red[1] + red[2] + red[3];
        float s_new = dot * SCALE_ + mask[C];
        float M = s_new;
        for (int j = 0; j < nchunks; j++) M = fmaxf(M, sm[j]);
        sMax = M;
        sSnew = s_new;
    }
    __syncthreads();
    float M = sMax;
    if (t < nchunks) sw[t] = expf(sm[t] - M);
    __syncthreads();
    if (t < 64) {
        float lv = 0.f;
        for (int j = t; j < nchunks; j += 64) lv += sw[j] * sl[j];
        float ws = warpSum(lv);
        if (t == 0) red[0] = ws;
        if (t == 32) red[1] = ws;
    }
    __syncthreads();
    if (t == 0) sL = expf(sSnew - M) + red[0] + red[1];
    __syncthreads();

    int d = t & 127;
    int cg = t >> 7;
    const float* accb = g_acc + (size_t)qh * MAXCH_ * DH_ + d;
    float a = 0.f;
    #pragma unroll 8
    for (int j = cg; j < nchunks; j += 4)
        a += sw[j] * accb[(size_t)j * DH_];
    vacc[t] = a;
    __syncthreads();
    if (t < 128) {
        float wnew = expf(sSnew - M);
        float tot = vacc[t] + vacc[t + 128] + vacc[t + 256] + vacc[t + 384]
                  + wnew * g_v[kv * DH_ + t];
        g_attn[qh * DH_ + t] = tot / sL;
    }
}

// ------------------------- 5: o_proj (R2 shape) ------------------------------
__global__ void k_oproj(const float* __restrict__ Wo, float* __restrict__ out) {
    int i = blockIdx.x, t = threadIdx.x;
    const float4* W4 = (const float4*)(Wo + (size_t)i * (HQ_ * DH_));
    const float4* a4 = (const float4*)g_attn;
    float acc = 0.f;
    #pragma unroll
    for (int k = 0; k < 4; k++) {
        float4 w = W4[t + k * 128];
        float4 a = a4[t + k * 128];
        acc += w.x * a.x + w.y * a.y + w.z * a.z + w.w * a.w;
    }
    __shared__ float s[4];
    float ws = warpSum(acc);
    if ((t & 31) == 0) s[t >> 5] = ws;
    __syncthreads();
    if (t == 0) out[i] = s[0] + s[1] + s[2] + s[3];
}

// ------------------------- launch --------------------------------------------
extern "C" void kernel_launch(void* const* d_in, const int* in_sizes, int n_in,
                              void* d_out, int out_size) {
    const float* x     = (const float*)d_in[0];
    const float* cosv  = (const float*)d_in[1];
    const float* sinv  = (const float*)d_in[2];
    const float* mask  = (const float*)d_in[3];
    const float* kc    = (const float*)d_in[4];
    const float* vc    = (const float*)d_in[5];
    const float* Wq    = (const float*)d_in[6];
    const float* Wk    = (const float*)d_in[7];
    const float* Wv    = (const float*)d_in[8];
    const float* Wo    = (const float*)d_in[9];
    const float* qw    = (const float*)d_in[10];
    const float* kw    = (const float*)d_in[11];
    float* out = (float*)d_out;

    int C = in_sizes[4] / (HKV_ * DH_);           // 16384
    int nchunks = (C + CHUNK_ - 1) / CHUNK_;      // 64
    if (nchunks > MAXCH_) nchunks = MAXCH_;

    k_proj<<<4096, 128>>>(x, Wq, Wk, Wv);
    k_norm_rope<<<32, 128>>>(cosv, sinv, qw, kw, out);
    dim3 g3(nchunks, HKV_);
    k_attn_partial<<<g3, 256>>>(kc, vc, mask, C);
    k_attn_reduce<<<HQ_, 512>>>(mask, C, nchunks);
    k_oproj<<<2048, 128>>>(Wo, out);
}